// round 14
// baseline (speedup 1.0000x reference)
#include <cuda_runtime.h>
#include <cstdint>

// ACT-LSTM persistent kernel, v9 = v4 structure + 256-bit L2::evict_last
// weight loads (sm_103a requires evict_last on .v8.b32). W_hh/W_out streams
// use v8 loads (32B/lane: 2x bytes-in-flight, half the LDG count) with
// evict_last to pin the 109MB weight set in GB300's 126MB L2 across graph
// replays. W_ih inner columns are only 4B-aligned (row stride 1025) -> plain
// __ldg scalar.
//
// I=1024, H=2048, O=1024, 4H=8192, MAX_STEPS=20.

#define NBLOCK 128
#define NTHREAD 1024
#define WPB (NTHREAD / 32)            // 32 warps/block
#define HDIM 2048
#define IDIM 1024
#define ODIM 1024
#define G4 (4 * HDIM)                 // 8192
#define MAX_STEPS 20

// -------- device scratch (no allocation allowed) --------
__device__ float g_gates[2][G4];
__device__ float g_gx_buf[G4];

// -------- manual grid barrier --------
__device__ unsigned g_bar_count = 0;
__device__ volatile unsigned g_bar_gen = 0;

__device__ __forceinline__ void grid_sync() {
    __syncthreads();
    if (threadIdx.x == 0) {
        __threadfence();
        unsigned gen = g_bar_gen;
        if (atomicAdd(&g_bar_count, 1u) == NBLOCK - 1) {
            g_bar_count = 0u;
            __threadfence();
            g_bar_gen = gen + 1u;
        } else {
            while (g_bar_gen == gen) { __nanosleep(32); }
            __threadfence();
        }
    }
    __syncthreads();
}

__device__ __forceinline__ float warp_reduce(float v) {
    #pragma unroll
    for (int off = 16; off; off >>= 1) v += __shfl_xor_sync(0xffffffffu, v, off);
    return v;
}

__device__ __forceinline__ float sigmoidf_(float x) {
    return 1.0f / (1.0f + __expf(-x));
}

__device__ __forceinline__ float dot4(float4 a, float4 b) {
    return a.x * b.x + a.y * b.y + a.z * b.z + a.w * b.w;
}

// 256-bit evict_last load: 8 floats from a 32B-aligned address.
__device__ __forceinline__ void ldg_el8(const float* p, float4& a, float4& b) {
    unsigned r0, r1, r2, r3, r4, r5, r6, r7;
    asm("ld.global.nc.L2::evict_last.v8.b32 {%0,%1,%2,%3,%4,%5,%6,%7}, [%8];"
        : "=r"(r0), "=r"(r1), "=r"(r2), "=r"(r3),
          "=r"(r4), "=r"(r5), "=r"(r6), "=r"(r7)
        : "l"(p));
    a.x = __uint_as_float(r0); a.y = __uint_as_float(r1);
    a.z = __uint_as_float(r2); a.w = __uint_as_float(r3);
    b.x = __uint_as_float(r4); b.y = __uint_as_float(r5);
    b.z = __uint_as_float(r6); b.w = __uint_as_float(r7);
}

__global__ __launch_bounds__(NTHREAD, 1)
void act_lstm_kernel(const float* __restrict__ x,
                     const float* __restrict__ h0,
                     const float* __restrict__ c0,
                     const float* __restrict__ W_ih,
                     const float* __restrict__ W_hh,
                     const float* __restrict__ b_ih,
                     const float* __restrict__ b_hh,
                     const float* __restrict__ w_halt,
                     const float* __restrict__ b_halt,
                     const float* __restrict__ W_out,
                     const float* __restrict__ b_out,
                     float* __restrict__ out) {
    __shared__ float sh_h[HDIM];
    __shared__ float sh_c[HDIM];
    __shared__ float sh_x[IDIM];
    __shared__ float s_red[WPB];

    const int tid   = threadIdx.x;
    const int lane  = tid & 31;
    const int warp  = tid >> 5;
    const int gwarp = blockIdx.x * WPB + warp;
    const int r0    = gwarp * 2;          // this warp's 2 gate rows

    // ---- init block-local state ----
    for (int j = tid; j < HDIM; j += NTHREAD) {
        sh_h[j] = h0[j];
        sh_c[j] = c0[j];
    }
    if (tid < IDIM) sh_x[tid] = x[tid];
    const float bh = b_halt[0];
    __syncthreads();

    // ---- fused phase: gates(t=0) = W_ih@[1,x] + b_ih + b_hh + W_hh@h0 ----
    {
        const float* wi0 = W_ih + (size_t)r0 * (IDIM + 1);
        const float* wi1 = wi0 + (IDIM + 1);
        float ai0 = 0.f, ai1 = 0.f;
        #pragma unroll 8
        for (int k = lane; k < IDIM; k += 32) {
            float xv = sh_x[k];
            ai0 += __ldg(wi0 + 1 + k) * xv;
            ai1 += __ldg(wi1 + 1 + k) * xv;
        }

        const float* wh0 = W_hh + (size_t)r0 * HDIM;
        const float* wh1 = wh0 + HDIM;
        float ah0 = 0.f, ah1 = 0.f;
        #pragma unroll
        for (int k = lane; k < HDIM / 8; k += 32) {       // 8 iterations
            const float* hp = sh_h + k * 8;
            float4 hA = *(const float4*)hp;
            float4 hB = *(const float4*)(hp + 4);
            float4 wa, wb, wc, wd;
            ldg_el8(wh0 + k * 8, wa, wb);
            ldg_el8(wh1 + k * 8, wc, wd);
            ah0 += dot4(wa, hA) + dot4(wb, hB);
            ah1 += dot4(wc, hA) + dot4(wd, hB);
        }

        ai0 = warp_reduce(ai0); ai1 = warp_reduce(ai1);
        ah0 = warp_reduce(ah0); ah1 = warp_reduce(ah1);

        if (lane == 0) {
            float b0 = ai0 + b_ih[r0 + 0] + b_hh[r0 + 0];
            float b1 = ai1 + b_ih[r0 + 1] + b_hh[r0 + 1];
            g_gx_buf[r0 + 0] = b0;
            g_gx_buf[r0 + 1] = b1;
            g_gates[0][r0 + 0] = b0 + __ldg(wi0) + ah0;   // flag col at t=0
            g_gates[0][r0 + 1] = b1 + __ldg(wi1) + ah1;
        }
    }
    grid_sync();

    // ---- adaptive loop: ONE grid barrier per step ----
    float cum = 0.0f;
    int   halted_t = MAX_STEPS - 1;
    int   buf = 0;

    for (int t = 0; t < MAX_STEPS; ++t) {
        // phase B: activations + halt (redundant per block, block-local state)
        const float* gt = g_gates[buf];
        float part = 0.0f;
        #pragma unroll
        for (int j = tid; j < HDIM; j += NTHREAD) {
            float gi = gt[j];
            float gf = gt[HDIM + j];
            float gg = gt[2 * HDIM + j];
            float go = gt[3 * HDIM + j];
            float cn = sigmoidf_(gf) * sh_c[j] + sigmoidf_(gi) * tanhf(gg);
            float hn = sigmoidf_(go) * tanhf(cn);
            sh_c[j] = cn;
            sh_h[j] = hn;
            part += w_halt[j] * hn;
        }
        part = warp_reduce(part);
        if (lane == 0) s_red[warp] = part;
        __syncthreads();
        float dot = 0.0f;
        #pragma unroll
        for (int w2 = 0; w2 < WPB; ++w2) dot += s_red[w2];
        float p = sigmoidf_(dot + bh);
        cum += p;
        if (cum >= 0.99f || t == MAX_STEPS - 1) { halted_t = t; break; }

        // phase A for step t+1: gates = gx + W_hh @ h (2 rows/warp, v8 loads)
        buf ^= 1;
        float* gn = g_gates[buf];
        {
            const float* wh0 = W_hh + (size_t)r0 * HDIM;
            const float* wh1 = wh0 + HDIM;
            float ah0 = 0.f, ah1 = 0.f;
            #pragma unroll
            for (int k = lane; k < HDIM / 8; k += 32) {
                const float* hp = sh_h + k * 8;
                float4 hA = *(const float4*)hp;
                float4 hB = *(const float4*)(hp + 4);
                float4 wa, wb, wc, wd;
                ldg_el8(wh0 + k * 8, wa, wb);
                ldg_el8(wh1 + k * 8, wc, wd);
                ah0 += dot4(wa, hA) + dot4(wb, hB);
                ah1 += dot4(wc, hA) + dot4(wd, hB);
            }
            ah0 = warp_reduce(ah0);
            ah1 = warp_reduce(ah1);
            if (lane == 0) {
                gn[r0 + 0] = g_gx_buf[r0 + 0] + ah0;
                gn[r0 + 1] = g_gx_buf[r0 + 1] + ah1;
            }
        }
        grid_sync();
    }

    // ---- epilogue (barrier-free): out = W_out @ h + b_out ----
    // Each W_out row split across 4 warps (k-quarter each, v8 loads).
    __syncthreads();
    {
        const int row = gwarp >> 2;          // 0..1023
        const int q   = gwarp & 3;           // k-quarter (512 floats)
        const float* wr = W_out + (size_t)row * HDIM + q * (HDIM / 4);
        const float* hq = sh_h + q * (HDIM / 4);
        float a = 0.f;
        #pragma unroll
        for (int k = lane; k < HDIM / 32; k += 32) {   // 64 v8-units, 2 iters
            const float* hp = hq + k * 8;
            float4 hA = *(const float4*)hp;
            float4 hB = *(const float4*)(hp + 4);
            float4 wa, wb;
            ldg_el8(wr + k * 8, wa, wb);
            a += dot4(wa, hA) + dot4(wb, hB);
        }
        a = warp_reduce(a);
        if (lane == 0) s_red[warp] = a;
        __syncthreads();
        if ((warp & 3) == 0 && lane == 0) {
            out[row] = s_red[warp] + s_red[warp + 1] + s_red[warp + 2]
                     + s_red[warp + 3] + b_out[row];
        }
    }

    if (blockIdx.x == 0) {
        for (int j = tid; j < HDIM; j += NTHREAD) {
            out[ODIM + j]        = sh_h[j];
            out[ODIM + HDIM + j] = sh_c[j];
        }
        if (tid == 0) out[ODIM + 2 * HDIM] = (float)halted_t;
    }
}

extern "C" void kernel_launch(void* const* d_in, const int* in_sizes, int n_in,
                              void* d_out, int out_size) {
    (void)in_sizes; (void)n_in; (void)out_size;
    const float* x      = (const float*)d_in[0];
    const float* h0     = (const float*)d_in[1];
    const float* c0     = (const float*)d_in[2];
    const float* W_ih   = (const float*)d_in[3];
    const float* W_hh   = (const float*)d_in[4];
    const float* b_ih   = (const float*)d_in[5];
    const float* b_hh   = (const float*)d_in[6];
    const float* w_halt = (const float*)d_in[7];
    const float* b_halt = (const float*)d_in[8];
    const float* W_out  = (const float*)d_in[9];
    const float* b_out  = (const float*)d_in[10];
    float* out = (float*)d_out;

    act_lstm_kernel<<<NBLOCK, NTHREAD>>>(x, h0, c0, W_ih, W_hh, b_ih, b_hh,
                                         w_halt, b_halt, W_out, b_out, out);
}

// round 15
// speedup vs baseline: 1.6632x; 1.6632x over previous
#include <cuda_runtime.h>
#include <cstdint>

// ACT-LSTM persistent kernel, v10.
// Fused t=0 pass streams weights with cp.async.bulk (UBLKCP): ONE 64KB bulk
// copy per stage into double-buffered shared memory, mbarrier completion.
// 12 stages/block (4x W_ih flat 65600B + 8x W_hh flat 65536B). No register
// pressure on the load path -> 128KB in flight per SM, HBM-bound streaming.
// Block bx owns gate rows [64bx, 64bx+64); W_ih region is flat-contiguous
// and 128B aligned (65600*4*bx). Phase B / cold phase A / epilogue = v4.
//
// I=1024, H=2048, O=1024, 4H=8192, MAX_STEPS=20.

#define NBLOCK 128
#define NTHREAD 1024
#define WPB 32
#define HDIM 2048
#define IDIM 1024
#define ODIM 1024
#define G4 (4 * HDIM)
#define MAX_STEPS 20
#define RPB 64                    // gate rows per block
#define IH_STG_FLOATS (16 * 1025) // 16400
#define HH_STG_FLOATS (8 * 2048)  // 16384
#define BUF_FLOATS IH_STG_FLOATS
#define NSTG 12                   // 4 W_ih + 8 W_hh

// dynamic smem layout (floats):
// buf0[16400] buf1[16400] sh_h[2048] sh_c[2048] sh_x[1024]
// s_ih2[128] s_hh4[256] s_flag[64] s_red[32] mbar[4 floats = 2x u64]
#define SMEM_FLOATS (2 * BUF_FLOATS + HDIM + HDIM + IDIM + 128 + 256 + 64 + 32 + 4)
#define SMEM_BYTES (SMEM_FLOATS * 4)

__device__ float g_gates[2][G4];
__device__ float g_gx_buf[G4];

__device__ unsigned g_bar_count = 0;
__device__ volatile unsigned g_bar_gen = 0;

__device__ __forceinline__ void grid_sync() {
    __syncthreads();
    if (threadIdx.x == 0) {
        __threadfence();
        unsigned gen = g_bar_gen;
        if (atomicAdd(&g_bar_count, 1u) == NBLOCK - 1) {
            g_bar_count = 0u;
            __threadfence();
            g_bar_gen = gen + 1u;
        } else {
            while (g_bar_gen == gen) { __nanosleep(32); }
            __threadfence();
        }
    }
    __syncthreads();
}

__device__ __forceinline__ float warp_reduce(float v) {
    #pragma unroll
    for (int off = 16; off; off >>= 1) v += __shfl_xor_sync(0xffffffffu, v, off);
    return v;
}

__device__ __forceinline__ float sigmoidf_(float x) {
    return 1.0f / (1.0f + __expf(-x));
}

__device__ __forceinline__ float dot4(float4 a, float4 b) {
    return a.x * b.x + a.y * b.y + a.z * b.z + a.w * b.w;
}

__device__ __forceinline__ void mbar_init(uint32_t mb, uint32_t count) {
    asm volatile("mbarrier.init.shared.b64 [%0], %1;" :: "r"(mb), "r"(count) : "memory");
}
__device__ __forceinline__ void mbar_expect_tx(uint32_t mb, uint32_t bytes) {
    asm volatile("mbarrier.arrive.expect_tx.shared.b64 _, [%0], %1;"
                 :: "r"(mb), "r"(bytes) : "memory");
}
__device__ __forceinline__ void bulk_g2s(uint32_t dst, const void* src,
                                         uint32_t bytes, uint32_t mb) {
    asm volatile("cp.async.bulk.shared::cta.global.mbarrier::complete_tx::bytes "
                 "[%0], [%1], %2, [%3];"
                 :: "r"(dst), "l"(src), "r"(bytes), "r"(mb) : "memory");
}
__device__ __forceinline__ void mbar_wait(uint32_t mb, uint32_t parity) {
    uint32_t done;
    asm volatile(
        "{\n\t.reg .pred p;\n\t"
        "mbarrier.try_wait.parity.acquire.cta.shared::cta.b64 p, [%1], %2;\n\t"
        "selp.b32 %0, 1, 0, p;\n\t}"
        : "=r"(done) : "r"(mb), "r"(parity) : "memory");
    if (!done) {
        asm volatile(
            "{\n\t.reg .pred P1;\n\t"
            "W_%=:\n\t"
            "mbarrier.try_wait.parity.acquire.cta.shared::cta.b64 P1, [%0], %1, 0x989680;\n\t"
            "@P1 bra.uni D_%=;\n\t"
            "bra.uni W_%=;\n\t"
            "D_%=:\n\t}"
            :: "r"(mb), "r"(parity) : "memory");
    }
}

__global__ __launch_bounds__(NTHREAD, 1)
void act_lstm_kernel(const float* __restrict__ x,
                     const float* __restrict__ h0,
                     const float* __restrict__ c0,
                     const float* __restrict__ W_ih,
                     const float* __restrict__ W_hh,
                     const float* __restrict__ b_ih,
                     const float* __restrict__ b_hh,
                     const float* __restrict__ w_halt,
                     const float* __restrict__ b_halt,
                     const float* __restrict__ W_out,
                     const float* __restrict__ b_out,
                     float* __restrict__ out) {
    extern __shared__ float smem[];
    float* buf[2];
    buf[0] = smem;
    buf[1] = smem + BUF_FLOATS;
    float* sh_h   = smem + 2 * BUF_FLOATS;
    float* sh_c   = sh_h + HDIM;
    float* sh_x   = sh_c + HDIM;
    float* s_ih2  = sh_x + IDIM;       // [RPB*2]
    float* s_hh4  = s_ih2 + 128;       // [RPB*4]
    float* s_flag = s_hh4 + 256;       // [RPB]
    float* s_red  = s_flag + 64;       // [32]
    float* s_mbar = s_red + 32;        // 2x u64

    const int tid  = threadIdx.x;
    const int lane = tid & 31;
    const int warp = tid >> 5;
    const int bx   = blockIdx.x;
    const int r0blk = bx * RPB;

    uint32_t mb0 = (uint32_t)__cvta_generic_to_shared(s_mbar);
    uint32_t mb1 = mb0 + 8;
    uint32_t bufaddr0 = (uint32_t)__cvta_generic_to_shared(buf[0]);
    uint32_t bufaddr1 = (uint32_t)__cvta_generic_to_shared(buf[1]);

    // ---- init state + mbarriers ----
    for (int j = tid; j < HDIM; j += NTHREAD) {
        sh_h[j] = h0[j];
        sh_c[j] = c0[j];
    }
    if (tid < IDIM) sh_x[tid] = x[tid];
    if (tid == 0) { mbar_init(mb0, 1); mbar_init(mb1, 1); }
    const float bh = b_halt[0];
    __syncthreads();

    // ---- producer: one bulk copy per stage ----
    auto produce = [&](int s) {
        if (s >= NSTG || tid != 0) return;
        uint32_t mb  = (s & 1) ? mb1 : mb0;
        uint32_t dst = (s & 1) ? bufaddr1 : bufaddr0;
        const float* src;
        uint32_t bytes;
        if (s < 4) {
            src = W_ih + (size_t)bx * (RPB * (IDIM + 1)) + (size_t)s * IH_STG_FLOATS;
            bytes = IH_STG_FLOATS * 4;     // 65600
        } else {
            src = W_hh + ((size_t)r0blk + 8 * (s - 4)) * HDIM;
            bytes = HH_STG_FLOATS * 4;     // 65536
        }
        mbar_expect_tx(mb, bytes);
        bulk_g2s(dst, src, bytes, mb);
    };

    produce(0);
    produce(1);

    // ---- consume 12 stages ----
    for (int s = 0; s < NSTG; ++s) {
        uint32_t mb = (s & 1) ? mb1 : mb0;
        mbar_wait(mb, (s >> 1) & 1);
        const float* bp = buf[s & 1];

        if (s < 4) {
            // 16 W_ih rows (1025 floats each incl flag); 2 warps/row, 512 cols each
            const int rl = warp >> 1;           // 0..15
            const int hf = warp & 1;
            const float* rowp = bp + rl * 1025;
            const float* p  = rowp + 1 + hf * 512 + lane;
            const float* xs = sh_x + hf * 512 + lane;
            float a = 0.f;
            #pragma unroll
            for (int i = 0; i < 16; ++i) a += p[i * 32] * xs[i * 32];
            a = warp_reduce(a);
            if (lane == 0) s_ih2[(16 * s + rl) * 2 + hf] = a;
            if (lane == 1 && hf == 0) s_flag[16 * s + rl] = rowp[0];
        } else {
            // 8 W_hh rows (2048 floats); 4 warps/row, 512 cols each
            const int s2 = s - 4;
            const int rl = warp >> 2;           // 0..7
            const int q  = warp & 3;
            const float4* w4 = (const float4*)(bp + rl * HDIM + q * 512);
            const float4* h4 = (const float4*)(sh_h + q * 512);
            float a = 0.f;
            #pragma unroll
            for (int i = 0; i < 4; ++i)
                a += dot4(w4[lane + i * 32], h4[lane + i * 32]);
            a = warp_reduce(a);
            if (lane == 0) s_hh4[(8 * s2 + rl) * 4 + q] = a;
        }
        __syncthreads();       // everyone done with buf (s&1)
        produce(s + 2);
    }

    // ---- combine partials -> gates(t=0) ----
    if (tid < RPB) {
        const int r = r0blk + tid;
        float ih = s_ih2[tid * 2] + s_ih2[tid * 2 + 1] + b_ih[r] + b_hh[r];
        float hh = (s_hh4[tid * 4] + s_hh4[tid * 4 + 1])
                 + (s_hh4[tid * 4 + 2] + s_hh4[tid * 4 + 3]);
        g_gx_buf[r] = ih;
        g_gates[0][r] = ih + s_flag[tid] + hh;   // flag col active at t=0
    }
    grid_sync();

    // ---- adaptive loop: ONE grid barrier per step ----
    float cum = 0.0f;
    int   halted_t = MAX_STEPS - 1;
    int   gbuf = 0;

    for (int t = 0; t < MAX_STEPS; ++t) {
        const float* gt = g_gates[gbuf];
        float part = 0.0f;
        #pragma unroll
        for (int j = tid; j < HDIM; j += NTHREAD) {
            float gi = gt[j];
            float gf = gt[HDIM + j];
            float gg = gt[2 * HDIM + j];
            float go = gt[3 * HDIM + j];
            float cn = sigmoidf_(gf) * sh_c[j] + sigmoidf_(gi) * tanhf(gg);
            float hn = sigmoidf_(go) * tanhf(cn);
            sh_c[j] = cn;
            sh_h[j] = hn;
            part += w_halt[j] * hn;
        }
        part = warp_reduce(part);
        if (lane == 0) s_red[warp] = part;
        __syncthreads();
        float dot = 0.0f;
        #pragma unroll
        for (int w2 = 0; w2 < WPB; ++w2) dot += s_red[w2];
        float p = sigmoidf_(dot + bh);
        cum += p;
        if (cum >= 0.99f || t == MAX_STEPS - 1) { halted_t = t; break; }

        // cold phase A for t+1 (v4-style LDG): gates = gx + W_hh @ h
        gbuf ^= 1;
        float* gn = g_gates[gbuf];
        {
            const int r0 = r0blk + warp * 2;
            const float4* wh0 = (const float4*)(W_hh + (size_t)r0 * HDIM);
            const float4* wh1 = wh0 + (HDIM / 4);
            const float4* hv  = (const float4*)sh_h;
            float ah0 = 0.f, ah1 = 0.f;
            #pragma unroll 4
            for (int k = lane; k < HDIM / 4; k += 32) {
                float4 h4 = hv[k];
                float4 w0 = __ldg(wh0 + k);
                float4 w1 = __ldg(wh1 + k);
                ah0 += dot4(w0, h4);
                ah1 += dot4(w1, h4);
            }
            ah0 = warp_reduce(ah0);
            ah1 = warp_reduce(ah1);
            if (lane == 0) {
                gn[r0 + 0] = g_gx_buf[r0 + 0] + ah0;
                gn[r0 + 1] = g_gx_buf[r0 + 1] + ah1;
            }
        }
        grid_sync();
    }

    // ---- epilogue (barrier-free): out = W_out @ h + b_out ----
    __syncthreads();
    {
        const int gwarp = bx * WPB + warp;
        const int row = gwarp >> 2;
        const int q   = gwarp & 3;
        const float4* wr = (const float4*)(W_out + (size_t)row * HDIM) + q * (HDIM / 16);
        const float4* hv = (const float4*)sh_h + q * (HDIM / 16);
        float a = 0.f;
        #pragma unroll 4
        for (int k = lane; k < HDIM / 16; k += 32) {
            float4 w  = __ldg(wr + k);
            float4 h4 = hv[k];
            a += dot4(w, h4);
        }
        a = warp_reduce(a);
        if (lane == 0) s_red[warp] = a;
        __syncthreads();
        if ((warp & 3) == 0 && lane == 0) {
            out[row] = s_red[warp] + s_red[warp + 1] + s_red[warp + 2]
                     + s_red[warp + 3] + b_out[row];
        }
    }

    if (bx == 0) {
        for (int j = tid; j < HDIM; j += NTHREAD) {
            out[ODIM + j]        = sh_h[j];
            out[ODIM + HDIM + j] = sh_c[j];
        }
        if (tid == 0) out[ODIM + 2 * HDIM] = (float)halted_t;
    }
}

extern "C" void kernel_launch(void* const* d_in, const int* in_sizes, int n_in,
                              void* d_out, int out_size) {
    (void)in_sizes; (void)n_in; (void)out_size;
    const float* x      = (const float*)d_in[0];
    const float* h0     = (const float*)d_in[1];
    const float* c0     = (const float*)d_in[2];
    const float* W_ih   = (const float*)d_in[3];
    const float* W_hh   = (const float*)d_in[4];
    const float* b_ih   = (const float*)d_in[5];
    const float* b_hh   = (const float*)d_in[6];
    const float* w_halt = (const float*)d_in[7];
    const float* b_halt = (const float*)d_in[8];
    const float* W_out  = (const float*)d_in[9];
    const float* b_out  = (const float*)d_in[10];
    float* out = (float*)d_out;

    cudaFuncSetAttribute(act_lstm_kernel,
                         cudaFuncAttributeMaxDynamicSharedMemorySize, SMEM_BYTES);
    act_lstm_kernel<<<NBLOCK, NTHREAD, SMEM_BYTES>>>(x, h0, c0, W_ih, W_hh,
                                                     b_ih, b_hh, w_halt, b_halt,
                                                     W_out, b_out, out);
}